// round 1
// baseline (speedup 1.0000x reference)
#include <cuda_runtime.h>
#include <math.h>

#define VIEWS 1024
#define SS 64
#define DD 256
#define M_TOTAL (VIEWS * SS)   // 65536

// Scratch (allocation-free rule: __device__ globals)
__device__ float g_qp[(size_t)M_TOTAL * DD];
__device__ float g_kp[(size_t)M_TOTAL * DD];
__device__ float g_vp[(size_t)M_TOTAL * DD];
__device__ float g_ao[(size_t)M_TOTAL * DD];
__device__ float g_pe[SS * DD];

// ---------------------------------------------------------------------------
// Positional encoding table (matches numpy float64 computation, cast to f32)
// ---------------------------------------------------------------------------
__global__ void posenc_kernel() {
    int idx = blockIdx.x * blockDim.x + threadIdx.x;
    if (idx >= SS * DD) return;
    int s = idx / DD;
    int d = idx % DD;
    double angle = (double)s / pow(10000.0, (2.0 * (double)(d / 2)) / (double)DD);
    g_pe[idx] = (d & 1) ? (float)cos(angle) : (float)sin(angle);
}

// ---------------------------------------------------------------------------
// SGEMM: C[M,256] = A[M,256] @ W[256,256]^T  (+ epilogue)
// MODE 0: C += pe[m % 64][n]
// MODE 1: C = gelu(C + bias[n]) + resid[m][n]     (exact gelu)
// Tiles: 128x128x8, 256 threads, 8x8 per-thread microtile, double buffered.
// ---------------------------------------------------------------------------
template<int MODE>
__global__ void __launch_bounds__(256, 2) gemm_k(
    const float* __restrict__ A, const float* __restrict__ W,
    float* __restrict__ C, const float* __restrict__ bias,
    const float* __restrict__ resid)
{
    __shared__ float As[2][8][128];
    __shared__ float Bs[2][8][128];

    const int m0 = blockIdx.x << 7;
    const int n0 = blockIdx.y << 7;
    const int t  = threadIdx.x;
    const int lrow = t >> 1;          // 0..127
    const int lk   = (t & 1) << 2;    // 0 or 4
    const int tx = t & 15;
    const int ty = t >> 4;

    const float* Ag = A + (m0 + lrow) * DD + lk;
    const float* Wg = W + (n0 + lrow) * DD + lk;

    float acc[8][8];
#pragma unroll
    for (int i = 0; i < 8; i++)
#pragma unroll
        for (int j = 0; j < 8; j++) acc[i][j] = 0.0f;

    float4 a4 = *(const float4*)Ag;
    float4 b4 = *(const float4*)Wg;
    As[0][lk+0][lrow] = a4.x; As[0][lk+1][lrow] = a4.y;
    As[0][lk+2][lrow] = a4.z; As[0][lk+3][lrow] = a4.w;
    Bs[0][lk+0][lrow] = b4.x; Bs[0][lk+1][lrow] = b4.y;
    Bs[0][lk+2][lrow] = b4.z; Bs[0][lk+3][lrow] = b4.w;
    __syncthreads();

    for (int kt = 0; kt < 32; kt++) {
        const int cur = kt & 1;
        if (kt < 31) {
            a4 = *(const float4*)(Ag + (kt + 1) * 8);
            b4 = *(const float4*)(Wg + (kt + 1) * 8);
        }
#pragma unroll
        for (int kk = 0; kk < 8; kk++) {
            float4 al = *(const float4*)&As[cur][kk][(ty << 2)];
            float4 ah = *(const float4*)&As[cur][kk][64 + (ty << 2)];
            float4 bl = *(const float4*)&Bs[cur][kk][(tx << 2)];
            float4 bh = *(const float4*)&Bs[cur][kk][64 + (tx << 2)];
            float ar[8] = {al.x, al.y, al.z, al.w, ah.x, ah.y, ah.z, ah.w};
            float br[8] = {bl.x, bl.y, bl.z, bl.w, bh.x, bh.y, bh.z, bh.w};
#pragma unroll
            for (int i = 0; i < 8; i++)
#pragma unroll
                for (int j = 0; j < 8; j++)
                    acc[i][j] = fmaf(ar[i], br[j], acc[i][j]);
        }
        if (kt < 31) {
            const int nx = cur ^ 1;
            As[nx][lk+0][lrow] = a4.x; As[nx][lk+1][lrow] = a4.y;
            As[nx][lk+2][lrow] = a4.z; As[nx][lk+3][lrow] = a4.w;
            Bs[nx][lk+0][lrow] = b4.x; Bs[nx][lk+1][lrow] = b4.y;
            Bs[nx][lk+2][lrow] = b4.z; Bs[nx][lk+3][lrow] = b4.w;
            __syncthreads();
        }
    }

#pragma unroll
    for (int ii = 0; ii < 8; ii++) {
        const int mr = m0 + ((ii < 4) ? ((ty << 2) + ii) : (64 + (ty << 2) + ii - 4));
        const int sr = mr & (SS - 1);
#pragma unroll
        for (int jh = 0; jh < 2; jh++) {
            const int nc = n0 + (jh << 6) + (tx << 2);
            float4 r;
            float* pr = &r.x;
#pragma unroll
            for (int c = 0; c < 4; c++) {
                float val = acc[ii][(jh << 2) + c];
                if (MODE == 0) {
                    val += g_pe[sr * DD + nc + c];
                } else {
                    float x = val + bias[nc + c];
                    val = 0.5f * x * (1.0f + erff(x * 0.70710678118654752f))
                        + resid[mr * DD + nc + c];
                }
                pr[c] = val;
            }
            *(float4*)&C[mr * DD + nc] = r;
        }
    }
}

// ---------------------------------------------------------------------------
// Per-ray attention: one block per ray (S=64, D=256).
// Q,K staged k-major in smem (pad 68, conflict-free), V row-major.
// scores -> stable softmax -> P@V.
// ---------------------------------------------------------------------------
#define PADQ 68
#define SMEM_ATTN ((256*PADQ*2 + 64*256 + 64*PADQ) * 4)   // 222208 bytes

__global__ void __launch_bounds__(256) attn_kernel(
    const float* __restrict__ QP, const float* __restrict__ KP,
    const float* __restrict__ VP, float* __restrict__ AO)
{
    extern __shared__ float sm[];
    float* Qs = sm;                    // [256][PADQ]  k-major
    float* Ks = Qs + 256 * PADQ;       // [256][PADQ]  k-major
    float* Vs = Ks + 256 * PADQ;       // [64][256]    row-major
    float* Ps = Vs + 64 * 256;         // [64][PADQ]   scores / probs

    const int t = threadIdx.x;
    const size_t base = (size_t)blockIdx.x * SS * DD;
    const float* qg = QP + base;
    const float* kg = KP + base;
    const float* vg = VP + base;

    // Load. Mapping chosen so transposed STS are stride-1 (conflict-free).
    for (int f = t; f < 4096; f += 256) {
        const int i  = f & 63;            // row within ray
        const int kq = (f >> 6) << 2;     // k offset (multiple of 4)
        float4 a = *(const float4*)(qg + i * DD + kq);
        Qs[(kq+0)*PADQ + i] = a.x; Qs[(kq+1)*PADQ + i] = a.y;
        Qs[(kq+2)*PADQ + i] = a.z; Qs[(kq+3)*PADQ + i] = a.w;
        float4 c = *(const float4*)(kg + i * DD + kq);
        Ks[(kq+0)*PADQ + i] = c.x; Ks[(kq+1)*PADQ + i] = c.y;
        Ks[(kq+2)*PADQ + i] = c.z; Ks[(kq+3)*PADQ + i] = c.w;
        float4 d = *(const float4*)(vg + (f << 2));     // straight copy
        *(float4*)(Vs + (f << 2)) = d;
    }
    __syncthreads();

    // Scores: S[i][j] = 0.0625 * dot(Qp[i], Kp[j]); 16x16 threads, 4x4 tile.
    {
        const int tx = t & 15, ty = t >> 4;
        float sacc[4][4];
#pragma unroll
        for (int i = 0; i < 4; i++)
#pragma unroll
            for (int j = 0; j < 4; j++) sacc[i][j] = 0.0f;

#pragma unroll 8
        for (int kk = 0; kk < 256; kk++) {
            float4 qv = *(const float4*)(Qs + kk * PADQ + (ty << 2));
            float4 kv = *(const float4*)(Ks + kk * PADQ + (tx << 2));
            float qa[4] = {qv.x, qv.y, qv.z, qv.w};
            float ka[4] = {kv.x, kv.y, kv.z, kv.w};
#pragma unroll
            for (int i = 0; i < 4; i++)
#pragma unroll
                for (int j = 0; j < 4; j++)
                    sacc[i][j] = fmaf(qa[i], ka[j], sacc[i][j]);
        }
#pragma unroll
        for (int i = 0; i < 4; i++) {
            float4 r = make_float4(sacc[i][0] * 0.0625f, sacc[i][1] * 0.0625f,
                                   sacc[i][2] * 0.0625f, sacc[i][3] * 0.0625f);
            *(float4*)(Ps + ((ty << 2) + i) * PADQ + (tx << 2)) = r;
        }
    }
    __syncthreads();

    // Softmax per row: warp w handles rows 8w..8w+7, 2 elems per lane.
    {
        const int w = t >> 5, lane = t & 31;
#pragma unroll
        for (int r = 0; r < 8; r++) {
            const int row = (w << 3) + r;
            float v0 = Ps[row * PADQ + lane];
            float v1 = Ps[row * PADQ + 32 + lane];
            float m = fmaxf(v0, v1);
#pragma unroll
            for (int o = 16; o > 0; o >>= 1)
                m = fmaxf(m, __shfl_xor_sync(0xffffffffu, m, o));
            float e0 = expf(v0 - m);
            float e1 = expf(v1 - m);
            float s = e0 + e1;
#pragma unroll
            for (int o = 16; o > 0; o >>= 1)
                s += __shfl_xor_sync(0xffffffffu, s, o);
            float inv = 1.0f / s;
            Ps[row * PADQ + lane]      = e0 * inv;
            Ps[row * PADQ + 32 + lane] = e1 * inv;
        }
    }
    __syncthreads();

    // Out[i][d] = sum_j P[i][j] * V[j][d]; 4x64 threads, each 16(i) x 4(d).
    {
        const int tx = t & 63, ty = t >> 6;   // ty: 0..3
        float acc[16][4];
#pragma unroll
        for (int i = 0; i < 16; i++)
#pragma unroll
            for (int c = 0; c < 4; c++) acc[i][c] = 0.0f;

        for (int jt = 0; jt < 16; jt++) {
            const int j0 = jt << 2;
            float pr[16][4];
#pragma unroll
            for (int ii = 0; ii < 16; ii++) {
                float4 pv = *(const float4*)(Ps + ((ty << 4) + ii) * PADQ + j0);
                pr[ii][0] = pv.x; pr[ii][1] = pv.y; pr[ii][2] = pv.z; pr[ii][3] = pv.w;
            }
#pragma unroll
            for (int jj = 0; jj < 4; jj++) {
                float4 vv = *(const float4*)(Vs + (j0 + jj) * DD + (tx << 2));
#pragma unroll
                for (int ii = 0; ii < 16; ii++) {
                    acc[ii][0] = fmaf(pr[ii][jj], vv.x, acc[ii][0]);
                    acc[ii][1] = fmaf(pr[ii][jj], vv.y, acc[ii][1]);
                    acc[ii][2] = fmaf(pr[ii][jj], vv.z, acc[ii][2]);
                    acc[ii][3] = fmaf(pr[ii][jj], vv.w, acc[ii][3]);
                }
            }
        }
#pragma unroll
        for (int ii = 0; ii < 16; ii++) {
            float4 r = make_float4(acc[ii][0], acc[ii][1], acc[ii][2], acc[ii][3]);
            *(float4*)(AO + base + ((ty << 4) + ii) * DD + (tx << 2)) = r;
        }
    }
}

// ---------------------------------------------------------------------------
extern "C" void kernel_launch(void* const* d_in, const int* in_sizes, int n_in,
                              void* d_out, int out_size) {
    (void)in_sizes; (void)n_in; (void)out_size;
    const float* q  = (const float*)d_in[0];
    const float* k  = (const float*)d_in[1];
    const float* v  = (const float*)d_in[2];
    const float* Wq = (const float*)d_in[3];
    const float* Wk = (const float*)d_in[4];
    const float* Wv = (const float*)d_in[5];
    const float* Wo = (const float*)d_in[6];
    const float* bo = (const float*)d_in[7];
    float* out = (float*)d_out;

    float *qp, *kp, *vp, *ao;
    cudaGetSymbolAddress((void**)&qp, g_qp);
    cudaGetSymbolAddress((void**)&kp, g_kp);
    cudaGetSymbolAddress((void**)&vp, g_vp);
    cudaGetSymbolAddress((void**)&ao, g_ao);

    posenc_kernel<<<(SS * DD + 255) / 256, 256>>>();

    dim3 gg(M_TOTAL / 128, DD / 128);
    gemm_k<0><<<gg, 256>>>(q, Wq, qp, nullptr, nullptr);
    gemm_k<0><<<gg, 256>>>(k, Wk, kp, nullptr, nullptr);
    gemm_k<0><<<gg, 256>>>(v, Wv, vp, nullptr, nullptr);

    cudaFuncSetAttribute(attn_kernel,
                         cudaFuncAttributeMaxDynamicSharedMemorySize, SMEM_ATTN);
    attn_kernel<<<VIEWS, 256, SMEM_ATTN>>>(qp, kp, vp, ao);

    gemm_k<1><<<gg, 256>>>(ao, Wo, out, bo, q);
}

// round 3
// speedup vs baseline: 1.3384x; 1.3384x over previous
#include <cuda_runtime.h>
#include <cuda_bf16.h>
#include <math.h>
#include <stdint.h>
#include <string.h>

#define VIEWS 1024
#define SS 64
#define DD 256
#define M_TOTAL (VIEWS * SS)   // 65536

// ---------------------------------------------------------------------------
// Scratch (allocation-free rule: __device__ globals)
// ---------------------------------------------------------------------------
__device__ float g_qp[(size_t)M_TOTAL * DD];
__device__ float g_kp[(size_t)M_TOTAL * DD];
__device__ float g_vp[(size_t)M_TOTAL * DD];
__device__ float g_ao[(size_t)M_TOTAL * DD];
__device__ float g_pe[SS * DD];
__device__ __nv_bfloat16 g_w_hi[4][DD * DD];
__device__ __nv_bfloat16 g_w_lo[4][DD * DD];

// ---------------------------------------------------------------------------
// sm_80-era PTX helpers (valid on base sm_103 target — NO tcgen05 here)
// ---------------------------------------------------------------------------
__device__ __forceinline__ uint32_t smem_to_u32(const void* p) {
    uint32_t a;
    asm("{ .reg .u64 t; cvta.to.shared.u64 t, %1; cvt.u32.u64 %0, t; }"
        : "=r"(a) : "l"(p));
    return a;
}
#define CP_ASYNC16(dst_u32, src_ptr) \
    asm volatile("cp.async.cg.shared.global [%0], [%1], 16;" \
        :: "r"(dst_u32), "l"(src_ptr))
#define CP_COMMIT() asm volatile("cp.async.commit_group;" ::: "memory")
#define CP_WAIT0()  asm volatile("cp.async.wait_group 0;" ::: "memory")

__device__ __forceinline__ void ldsm4(uint32_t* r, uint32_t addr) {
    asm volatile("ldmatrix.sync.aligned.m8n8.x4.shared.b16 {%0,%1,%2,%3}, [%4];"
        : "=r"(r[0]), "=r"(r[1]), "=r"(r[2]), "=r"(r[3]) : "r"(addr));
}
__device__ __forceinline__ void mma16816(float* c, const uint32_t* a, const uint32_t* b) {
    asm volatile(
        "mma.sync.aligned.m16n8k16.row.col.f32.bf16.bf16.f32 "
        "{%0,%1,%2,%3}, {%4,%5,%6,%7}, {%8,%9}, {%0,%1,%2,%3};"
        : "+f"(c[0]), "+f"(c[1]), "+f"(c[2]), "+f"(c[3])
        : "r"(a[0]), "r"(a[1]), "r"(a[2]), "r"(a[3]), "r"(b[0]), "r"(b[1]));
}

// ---------------------------------------------------------------------------
// Positional encoding table (matches numpy float64 computation, cast to f32)
// ---------------------------------------------------------------------------
__global__ void posenc_kernel() {
    int idx = blockIdx.x * blockDim.x + threadIdx.x;
    if (idx >= SS * DD) return;
    int s = idx / DD;
    int d = idx % DD;
    double angle = (double)s / pow(10000.0, (2.0 * (double)(d / 2)) / (double)DD);
    g_pe[idx] = (d & 1) ? (float)cos(angle) : (float)sin(angle);
}

// ---------------------------------------------------------------------------
// Weight split: fp32 W -> bf16 hi + bf16 lo (lo = bf16(x - f32(hi)))
// ---------------------------------------------------------------------------
__global__ void wsplit_kernel(const float* __restrict__ w,
                              __nv_bfloat16* __restrict__ hi,
                              __nv_bfloat16* __restrict__ lo) {
    int i = blockIdx.x * 256 + threadIdx.x;
    float x = w[i];
    __nv_bfloat16 h = __float2bfloat16_rn(x);
    hi[i] = h;
    lo[i] = __float2bfloat16_rn(x - __bfloat162float(h));
}

// ---------------------------------------------------------------------------
// HMMA GEMM: C[M,256] = A[M,256] @ W[256,256]^T via 3-term bf16 split.
// CTA tile 128x128, 256 thr (8 warps as 4m x 2n, warp tile 32x64).
// K = 4 chunks of 64. B (pre-split bf16) via cp.async; A fp32->split in regs.
// Stage layout (bytes, per stage of 65536): AHI 0, ALO 16384, BHI 32768, BLO 49152.
// Row = 64 bf16 = 128B; XOR swizzle on 16B units: unit ^= (row & 7).
// MODE 0: C += pe[m % 64][n] ; MODE 1: C = gelu(C + bias) + resid
// ---------------------------------------------------------------------------
#define GSMEM_TOTAL 131072

__device__ __forceinline__ uint32_t pack2bf(float a, float b) {
    __nv_bfloat162 h = __floats2bfloat162_rn(a, b);
    uint32_t u; memcpy(&u, &h, 4); return u;
}

template<int MODE>
__global__ void __launch_bounds__(256, 1) gemm_hmma(
    const float* __restrict__ A,
    const __nv_bfloat16* __restrict__ Whi,
    const __nv_bfloat16* __restrict__ Wlo,
    float* __restrict__ C,
    const float* __restrict__ bias,
    const float* __restrict__ resid)
{
    extern __shared__ char smem[];
    const uint32_t sbase = smem_to_u32(smem);
    const int t = threadIdx.x;
    const int wid = t >> 5, lane = t & 31;
    const int wm = wid >> 1, wn = wid & 1;
    const int m0 = blockIdx.x << 7;
    const int N0 = blockIdx.y << 7;

    float acc[2][8][4];
#pragma unroll
    for (int i = 0; i < 2; i++)
#pragma unroll
        for (int j = 0; j < 8; j++)
#pragma unroll
            for (int c = 0; c < 4; c++) acc[i][j][c] = 0.0f;

    // Per-thread load indices
    const int a_row = t >> 1;              // unused pattern; real one below
    (void)a_row;

    // ---- B loader (cp.async, 16B granules, swizzled) ----
    auto load_B = [&](int kc, int s) {
        const uint32_t bhi = sbase + s * 65536 + 32768;
        const uint32_t blo = bhi + 16384;
#pragma unroll
        for (int g = 0; g < 4; g++) {
            int idx = g * 256 + t;               // 0..1023
            int nrow = idx >> 3;                 // 128 rows, 8x16B per row
            int c16 = idx & 7;
            size_t goff = (size_t)(N0 + nrow) * DD + kc * 64 + c16 * 8;
            uint32_t d = (uint32_t)(nrow * 128 + ((c16 ^ (nrow & 7)) << 4));
            CP_ASYNC16(bhi + d, (const void*)(Whi + goff));
            CP_ASYNC16(blo + d, (const void*)(Wlo + goff));
        }
    };

    // ---- A loader: 8 float4 per thread ----
    float4 areg[8];
    auto load_A = [&](int kc) {
#pragma unroll
        for (int g = 0; g < 8; g++) {
            int idx = g * 256 + t;               // 0..2047
            int row = idx >> 4;                  // 16 float4 per row
            int f4c = idx & 15;
            areg[g] = *(const float4*)(A + (size_t)(m0 + row) * DD + kc * 64 + f4c * 4);
        }
    };
    auto store_A = [&](int s) {
        char* ahi = smem + s * 65536;
        char* alo = ahi + 16384;
#pragma unroll
        for (int g = 0; g < 8; g++) {
            int idx = g * 256 + t;
            int row = idx >> 4;
            int f4c = idx & 15;
            float4 v = areg[g];
            __nv_bfloat16 hx = __float2bfloat16_rn(v.x);
            __nv_bfloat16 hy = __float2bfloat16_rn(v.y);
            __nv_bfloat16 hz = __float2bfloat16_rn(v.z);
            __nv_bfloat16 hw = __float2bfloat16_rn(v.w);
            uint16_t ux, uy, uz, uw;
            memcpy(&ux, &hx, 2); memcpy(&uy, &hy, 2);
            memcpy(&uz, &hz, 2); memcpy(&uw, &hw, 2);
            uint64_t hi64 = (uint64_t)((uint32_t)ux | ((uint32_t)uy << 16))
                          | ((uint64_t)((uint32_t)uz | ((uint32_t)uw << 16)) << 32);
            uint64_t lo64 = (uint64_t)pack2bf(v.x - __bfloat162float(hx),
                                              v.y - __bfloat162float(hy))
                          | ((uint64_t)pack2bf(v.z - __bfloat162float(hz),
                                               v.w - __bfloat162float(hw)) << 32);
            int d = row * 128 + (((f4c >> 1) ^ (row & 7)) << 4) + ((f4c & 1) << 3);
            *(uint64_t*)(ahi + d) = hi64;
            *(uint64_t*)(alo + d) = lo64;
        }
    };

    // ---- Prologue: chunk 0 ----
    load_B(0, 0);
    CP_COMMIT();
    load_A(0);
    store_A(0);

    // Precompute per-lane LDSM address components
    const int q  = lane >> 3;
    const int r8 = lane & 7;
    int arow[2], brow[4];
#pragma unroll
    for (int mi = 0; mi < 2; mi++) arow[mi] = wm * 32 + mi * 16 + r8 + (q & 1) * 8;
#pragma unroll
    for (int ni = 0; ni < 4; ni++) brow[ni] = wn * 64 + ni * 16 + r8 + (q >> 1) * 8;
    const int a_kq = q >> 1;     // 16B-unit offset within k16 for A
    const int b_kq = q & 1;      // for B

    for (int kc = 0; kc < 4; kc++) {
        const int s = kc & 1;
        CP_WAIT0();
        __syncthreads();
        if (kc < 3) {
            load_B(kc + 1, s ^ 1);
            CP_COMMIT();
            load_A(kc + 1);      // LDGs in flight during MMA below
        }

        const uint32_t abase0 = sbase + s * 65536;
        const uint32_t bbase0 = abase0 + 32768;
#pragma unroll
        for (int term = 0; term < 3; term++) {
            const uint32_t abase = abase0 + ((term == 2) ? 16384u : 0u);
            const uint32_t bbase = bbase0 + ((term == 1) ? 16384u : 0u);
#pragma unroll
            for (int k16 = 0; k16 < 4; k16++) {
                uint32_t af[2][4], bf[4][4];
#pragma unroll
                for (int mi = 0; mi < 2; mi++) {
                    int ku = k16 * 2 + a_kq;
                    uint32_t addr = abase + arow[mi] * 128 + (((ku ^ (arow[mi] & 7))) << 4);
                    ldsm4(af[mi], addr);
                }
#pragma unroll
                for (int ni = 0; ni < 4; ni++) {
                    int ku = k16 * 2 + b_kq;
                    uint32_t addr = bbase + brow[ni] * 128 + (((ku ^ (brow[ni] & 7))) << 4);
                    ldsm4(bf[ni], addr);
                }
#pragma unroll
                for (int mi = 0; mi < 2; mi++)
#pragma unroll
                    for (int n8 = 0; n8 < 8; n8++)
                        mma16816(acc[mi][n8], af[mi], &bf[n8 >> 1][(n8 & 1) * 2]);
            }
        }
        if (kc < 3) store_A(s ^ 1);
    }

    // ---- Epilogue: direct from fragments, float2 stores ----
    const int fr = lane >> 2;          // 0..7
    const int fc = (lane & 3) * 2;     // 0,2,4,6
#pragma unroll
    for (int mi = 0; mi < 2; mi++) {
#pragma unroll
        for (int half = 0; half < 2; half++) {
            const int mrow = m0 + wm * 32 + mi * 16 + fr + half * 8;
            const int sr = mrow & (SS - 1);
#pragma unroll
            for (int n8 = 0; n8 < 8; n8++) {
                const int ncol = N0 + wn * 64 + n8 * 8 + fc;
                float v0 = acc[mi][n8][half * 2 + 0];
                float v1 = acc[mi][n8][half * 2 + 1];
                if (MODE == 0) {
                    float2 pe = *(const float2*)&g_pe[sr * DD + ncol];
                    v0 += pe.x; v1 += pe.y;
                } else {
                    float2 bb = *(const float2*)&bias[ncol];
                    float2 rr = *(const float2*)&resid[(size_t)mrow * DD + ncol];
                    float x0 = v0 + bb.x, x1 = v1 + bb.y;
                    v0 = 0.5f * x0 * (1.0f + erff(x0 * 0.70710678118654752f)) + rr.x;
                    v1 = 0.5f * x1 * (1.0f + erff(x1 * 0.70710678118654752f)) + rr.y;
                }
                float2 r = make_float2(v0, v1);
                *(float2*)&C[(size_t)mrow * DD + ncol] = r;
            }
        }
    }
}

// ---------------------------------------------------------------------------
// Per-ray attention (unchanged): one block per ray (S=64, D=256).
// ---------------------------------------------------------------------------
#define PADQ 68
#define SMEM_ATTN ((256*PADQ*2 + 64*256 + 64*PADQ) * 4)   // 222208 bytes

__global__ void __launch_bounds__(256) attn_kernel(
    const float* __restrict__ QP, const float* __restrict__ KP,
    const float* __restrict__ VP, float* __restrict__ AO)
{
    extern __shared__ float sm[];
    float* Qs = sm;
    float* Ks = Qs + 256 * PADQ;
    float* Vs = Ks + 256 * PADQ;
    float* Ps = Vs + 64 * 256;

    const int t = threadIdx.x;
    const size_t base = (size_t)blockIdx.x * SS * DD;
    const float* qg = QP + base;
    const float* kg = KP + base;
    const float* vg = VP + base;

    for (int f = t; f < 4096; f += 256) {
        const int i  = f & 63;
        const int kq = (f >> 6) << 2;
        float4 a = *(const float4*)(qg + i * DD + kq);
        Qs[(kq+0)*PADQ + i] = a.x; Qs[(kq+1)*PADQ + i] = a.y;
        Qs[(kq+2)*PADQ + i] = a.z; Qs[(kq+3)*PADQ + i] = a.w;
        float4 c = *(const float4*)(kg + i * DD + kq);
        Ks[(kq+0)*PADQ + i] = c.x; Ks[(kq+1)*PADQ + i] = c.y;
        Ks[(kq+2)*PADQ + i] = c.z; Ks[(kq+3)*PADQ + i] = c.w;
        float4 d = *(const float4*)(vg + (f << 2));
        *(float4*)(Vs + (f << 2)) = d;
    }
    __syncthreads();

    {
        const int tx = t & 15, ty = t >> 4;
        float sacc[4][4];
#pragma unroll
        for (int i = 0; i < 4; i++)
#pragma unroll
            for (int j = 0; j < 4; j++) sacc[i][j] = 0.0f;

#pragma unroll 8
        for (int kk = 0; kk < 256; kk++) {
            float4 qv = *(const float4*)(Qs + kk * PADQ + (ty << 2));
            float4 kv = *(const float4*)(Ks + kk * PADQ + (tx << 2));
            float qa[4] = {qv.x, qv.y, qv.z, qv.w};
            float ka[4] = {kv.x, kv.y, kv.z, kv.w};
#pragma unroll
            for (int i = 0; i < 4; i++)
#pragma unroll
                for (int j = 0; j < 4; j++)
                    sacc[i][j] = fmaf(qa[i], ka[j], sacc[i][j]);
        }
#pragma unroll
        for (int i = 0; i < 4; i++) {
            float4 r = make_float4(sacc[i][0] * 0.0625f, sacc[i][1] * 0.0625f,
                                   sacc[i][2] * 0.0625f, sacc[i][3] * 0.0625f);
            *(float4*)(Ps + ((ty << 2) + i) * PADQ + (tx << 2)) = r;
        }
    }
    __syncthreads();

    {
        const int w = t >> 5, lane = t & 31;
#pragma unroll
        for (int r = 0; r < 8; r++) {
            const int row = (w << 3) + r;
            float v0 = Ps[row * PADQ + lane];
            float v1 = Ps[row * PADQ + 32 + lane];
            float m = fmaxf(v0, v1);
#pragma unroll
            for (int o = 16; o > 0; o >>= 1)
                m = fmaxf(m, __shfl_xor_sync(0xffffffffu, m, o));
            float e0 = expf(v0 - m);
            float e1 = expf(v1 - m);
            float s = e0 + e1;
#pragma unroll
            for (int o = 16; o > 0; o >>= 1)
                s += __shfl_xor_sync(0xffffffffu, s, o);
            float inv = 1.0f / s;
            Ps[row * PADQ + lane]      = e0 * inv;
            Ps[row * PADQ + 32 + lane] = e1 * inv;
        }
    }
    __syncthreads();

    {
        const int tx = t & 63, ty = t >> 6;
        float acc[16][4];
#pragma unroll
        for (int i = 0; i < 16; i++)
#pragma unroll
            for (int c = 0; c < 4; c++) acc[i][c] = 0.0f;

        for (int jt = 0; jt < 16; jt++) {
            const int j0 = jt << 2;
            float pr[16][4];
#pragma unroll
            for (int ii = 0; ii < 16; ii++) {
                float4 pv = *(const float4*)(Ps + ((ty << 4) + ii) * PADQ + j0);
                pr[ii][0] = pv.x; pr[ii][1] = pv.y; pr[ii][2] = pv.z; pr[ii][3] = pv.w;
            }
#pragma unroll
            for (int jj = 0; jj < 4; jj++) {
                float4 vv = *(const float4*)(Vs + (j0 + jj) * DD + (tx << 2));
#pragma unroll
                for (int ii = 0; ii < 16; ii++) {
                    acc[ii][0] = fmaf(pr[ii][jj], vv.x, acc[ii][0]);
                    acc[ii][1] = fmaf(pr[ii][jj], vv.y, acc[ii][1]);
                    acc[ii][2] = fmaf(pr[ii][jj], vv.z, acc[ii][2]);
                    acc[ii][3] = fmaf(pr[ii][jj], vv.w, acc[ii][3]);
                }
            }
        }
#pragma unroll
        for (int ii = 0; ii < 16; ii++) {
            float4 r = make_float4(acc[ii][0], acc[ii][1], acc[ii][2], acc[ii][3]);
            *(float4*)(AO + base + ((ty << 4) + ii) * DD + (tx << 2)) = r;
        }
    }
}

// ---------------------------------------------------------------------------
extern "C" void kernel_launch(void* const* d_in, const int* in_sizes, int n_in,
                              void* d_out, int out_size) {
    (void)in_sizes; (void)n_in; (void)out_size;
    const float* q  = (const float*)d_in[0];
    const float* k  = (const float*)d_in[1];
    const float* v  = (const float*)d_in[2];
    const float* Wq = (const float*)d_in[3];
    const float* Wk = (const float*)d_in[4];
    const float* Wv = (const float*)d_in[5];
    const float* Wo = (const float*)d_in[6];
    const float* bo = (const float*)d_in[7];
    float* out = (float*)d_out;

    float *qp, *kp, *vp, *ao;
    cudaGetSymbolAddress((void**)&qp, g_qp);
    cudaGetSymbolAddress((void**)&kp, g_kp);
    cudaGetSymbolAddress((void**)&vp, g_vp);
    cudaGetSymbolAddress((void**)&ao, g_ao);
    __nv_bfloat16 *whi, *wlo;
    cudaGetSymbolAddress((void**)&whi, g_w_hi);
    cudaGetSymbolAddress((void**)&wlo, g_w_lo);

    posenc_kernel<<<(SS * DD + 255) / 256, 256>>>();
    wsplit_kernel<<<DD * DD / 256, 256>>>(Wq, whi + 0 * DD * DD, wlo + 0 * DD * DD);
    wsplit_kernel<<<DD * DD / 256, 256>>>(Wk, whi + 1 * DD * DD, wlo + 1 * DD * DD);
    wsplit_kernel<<<DD * DD / 256, 256>>>(Wv, whi + 2 * DD * DD, wlo + 2 * DD * DD);
    wsplit_kernel<<<DD * DD / 256, 256>>>(Wo, whi + 3 * DD * DD, wlo + 3 * DD * DD);

    cudaFuncSetAttribute(gemm_hmma<0>, cudaFuncAttributeMaxDynamicSharedMemorySize, GSMEM_TOTAL);
    cudaFuncSetAttribute(gemm_hmma<1>, cudaFuncAttributeMaxDynamicSharedMemorySize, GSMEM_TOTAL);
    cudaFuncSetAttribute(attn_kernel,  cudaFuncAttributeMaxDynamicSharedMemorySize, SMEM_ATTN);

    dim3 gg(M_TOTAL / 128, 2);
    gemm_hmma<0><<<gg, 256, GSMEM_TOTAL>>>(q, whi + 0 * DD * DD, wlo + 0 * DD * DD, qp, nullptr, nullptr);
    gemm_hmma<0><<<gg, 256, GSMEM_TOTAL>>>(k, whi + 1 * DD * DD, wlo + 1 * DD * DD, kp, nullptr, nullptr);
    gemm_hmma<0><<<gg, 256, GSMEM_TOTAL>>>(v, whi + 2 * DD * DD, wlo + 2 * DD * DD, vp, nullptr, nullptr);

    attn_kernel<<<VIEWS, 256, SMEM_ATTN>>>(qp, kp, vp, ao);

    gemm_hmma<1><<<gg, 256, GSMEM_TOTAL>>>(ao, whi + 3 * DD * DD, wlo + 3 * DD * DD, out, bo, q);
}

// round 4
// speedup vs baseline: 1.6010x; 1.1961x over previous
#include <cuda_runtime.h>
#include <cuda_bf16.h>
#include <math.h>
#include <stdint.h>
#include <string.h>

#define VIEWS 1024
#define SS 64
#define DD 256
#define M_TOTAL (VIEWS * SS)   // 65536

// ---------------------------------------------------------------------------
// Scratch (allocation-free rule: __device__ globals)
// ---------------------------------------------------------------------------
__device__ float g_qp[(size_t)M_TOTAL * DD];
__device__ float g_kp[(size_t)M_TOTAL * DD];
__device__ float g_vp[(size_t)M_TOTAL * DD];
__device__ float g_ao[(size_t)M_TOTAL * DD];
__device__ float g_pe[SS * DD];
__device__ __nv_bfloat16 g_w_hi[4][DD * DD];
__device__ __nv_bfloat16 g_w_lo[4][DD * DD];

// ---------------------------------------------------------------------------
// sm_80-era PTX helpers (valid on base sm_103 target — NO tcgen05 here)
// ---------------------------------------------------------------------------
__device__ __forceinline__ uint32_t smem_to_u32(const void* p) {
    uint32_t a;
    asm("{ .reg .u64 t; cvta.to.shared.u64 t, %1; cvt.u32.u64 %0, t; }"
        : "=r"(a) : "l"(p));
    return a;
}
#define CP_ASYNC16(dst_u32, src_ptr) \
    asm volatile("cp.async.cg.shared.global [%0], [%1], 16;" \
        :: "r"(dst_u32), "l"(src_ptr))
#define CP_COMMIT() asm volatile("cp.async.commit_group;" ::: "memory")
#define CP_WAIT0()  asm volatile("cp.async.wait_group 0;" ::: "memory")

__device__ __forceinline__ void ldsm4(uint32_t* r, uint32_t addr) {
    asm volatile("ldmatrix.sync.aligned.m8n8.x4.shared.b16 {%0,%1,%2,%3}, [%4];"
        : "=r"(r[0]), "=r"(r[1]), "=r"(r[2]), "=r"(r[3]) : "r"(addr));
}
__device__ __forceinline__ void ldsm4t(uint32_t* r, uint32_t addr) {
    asm volatile("ldmatrix.sync.aligned.m8n8.x4.trans.shared.b16 {%0,%1,%2,%3}, [%4];"
        : "=r"(r[0]), "=r"(r[1]), "=r"(r[2]), "=r"(r[3]) : "r"(addr));
}
__device__ __forceinline__ void mma16816(float* c, const uint32_t* a, const uint32_t* b) {
    asm volatile(
        "mma.sync.aligned.m16n8k16.row.col.f32.bf16.bf16.f32 "
        "{%0,%1,%2,%3}, {%4,%5,%6,%7}, {%8,%9}, {%0,%1,%2,%3};"
        : "+f"(c[0]), "+f"(c[1]), "+f"(c[2]), "+f"(c[3])
        : "r"(a[0]), "r"(a[1]), "r"(a[2]), "r"(a[3]), "r"(b[0]), "r"(b[1]));
}

// ---------------------------------------------------------------------------
// Positional encoding table
// ---------------------------------------------------------------------------
__global__ void posenc_kernel() {
    int idx = blockIdx.x * blockDim.x + threadIdx.x;
    if (idx >= SS * DD) return;
    int s = idx / DD;
    int d = idx % DD;
    double angle = (double)s / pow(10000.0, (2.0 * (double)(d / 2)) / (double)DD);
    g_pe[idx] = (d & 1) ? (float)cos(angle) : (float)sin(angle);
}

// ---------------------------------------------------------------------------
// Weight split: fp32 W -> bf16 hi + bf16 lo
// ---------------------------------------------------------------------------
__global__ void wsplit_kernel(const float* __restrict__ w,
                              __nv_bfloat16* __restrict__ hi,
                              __nv_bfloat16* __restrict__ lo) {
    int i = blockIdx.x * 256 + threadIdx.x;
    float x = w[i];
    __nv_bfloat16 h = __float2bfloat16_rn(x);
    hi[i] = h;
    lo[i] = __float2bfloat16_rn(x - __bfloat162float(h));
}

__device__ __forceinline__ uint32_t pack2bf(float a, float b) {
    __nv_bfloat162 h = __floats2bfloat162_rn(a, b);
    uint32_t u; memcpy(&u, &h, 4); return u;
}

// ---------------------------------------------------------------------------
// HMMA GEMM (unchanged from R3, validated): C = A @ W^T via 3-term bf16 split
// ---------------------------------------------------------------------------
#define GSMEM_TOTAL 131072

template<int MODE>
__global__ void __launch_bounds__(256, 1) gemm_hmma(
    const float* __restrict__ A,
    const __nv_bfloat16* __restrict__ Whi,
    const __nv_bfloat16* __restrict__ Wlo,
    float* __restrict__ C,
    const float* __restrict__ bias,
    const float* __restrict__ resid)
{
    extern __shared__ char smem[];
    const uint32_t sbase = smem_to_u32(smem);
    const int t = threadIdx.x;
    const int wid = t >> 5, lane = t & 31;
    const int wm = wid >> 1, wn = wid & 1;
    const int m0 = blockIdx.x << 7;
    const int N0 = blockIdx.y << 7;

    float acc[2][8][4];
#pragma unroll
    for (int i = 0; i < 2; i++)
#pragma unroll
        for (int j = 0; j < 8; j++)
#pragma unroll
            for (int c = 0; c < 4; c++) acc[i][j][c] = 0.0f;

    auto load_B = [&](int kc, int s) {
        const uint32_t bhi = sbase + s * 65536 + 32768;
        const uint32_t blo = bhi + 16384;
#pragma unroll
        for (int g = 0; g < 4; g++) {
            int idx = g * 256 + t;
            int nrow = idx >> 3;
            int c16 = idx & 7;
            size_t goff = (size_t)(N0 + nrow) * DD + kc * 64 + c16 * 8;
            uint32_t d = (uint32_t)(nrow * 128 + ((c16 ^ (nrow & 7)) << 4));
            CP_ASYNC16(bhi + d, (const void*)(Whi + goff));
            CP_ASYNC16(blo + d, (const void*)(Wlo + goff));
        }
    };

    float4 areg[8];
    auto load_A = [&](int kc) {
#pragma unroll
        for (int g = 0; g < 8; g++) {
            int idx = g * 256 + t;
            int row = idx >> 4;
            int f4c = idx & 15;
            areg[g] = *(const float4*)(A + (size_t)(m0 + row) * DD + kc * 64 + f4c * 4);
        }
    };
    auto store_A = [&](int s) {
        char* ahi = smem + s * 65536;
        char* alo = ahi + 16384;
#pragma unroll
        for (int g = 0; g < 8; g++) {
            int idx = g * 256 + t;
            int row = idx >> 4;
            int f4c = idx & 15;
            float4 v = areg[g];
            __nv_bfloat16 hx = __float2bfloat16_rn(v.x);
            __nv_bfloat16 hy = __float2bfloat16_rn(v.y);
            __nv_bfloat16 hz = __float2bfloat16_rn(v.z);
            __nv_bfloat16 hw = __float2bfloat16_rn(v.w);
            uint16_t ux, uy, uz, uw;
            memcpy(&ux, &hx, 2); memcpy(&uy, &hy, 2);
            memcpy(&uz, &hz, 2); memcpy(&uw, &hw, 2);
            uint64_t hi64 = (uint64_t)((uint32_t)ux | ((uint32_t)uy << 16))
                          | ((uint64_t)((uint32_t)uz | ((uint32_t)uw << 16)) << 32);
            uint64_t lo64 = (uint64_t)pack2bf(v.x - __bfloat162float(hx),
                                              v.y - __bfloat162float(hy))
                          | ((uint64_t)pack2bf(v.z - __bfloat162float(hz),
                                               v.w - __bfloat162float(hw)) << 32);
            int d = row * 128 + (((f4c >> 1) ^ (row & 7)) << 4) + ((f4c & 1) << 3);
            *(uint64_t*)(ahi + d) = hi64;
            *(uint64_t*)(alo + d) = lo64;
        }
    };

    load_B(0, 0);
    CP_COMMIT();
    load_A(0);
    store_A(0);

    const int q  = lane >> 3;
    const int r8 = lane & 7;
    int arow[2], brow[4];
#pragma unroll
    for (int mi = 0; mi < 2; mi++) arow[mi] = wm * 32 + mi * 16 + r8 + (q & 1) * 8;
#pragma unroll
    for (int ni = 0; ni < 4; ni++) brow[ni] = wn * 64 + ni * 16 + r8 + (q >> 1) * 8;
    const int a_kq = q >> 1;
    const int b_kq = q & 1;

    for (int kc = 0; kc < 4; kc++) {
        const int s = kc & 1;
        CP_WAIT0();
        __syncthreads();
        if (kc < 3) {
            load_B(kc + 1, s ^ 1);
            CP_COMMIT();
            load_A(kc + 1);
        }

        const uint32_t abase0 = sbase + s * 65536;
        const uint32_t bbase0 = abase0 + 32768;
#pragma unroll
        for (int term = 0; term < 3; term++) {
            const uint32_t abase = abase0 + ((term == 2) ? 16384u : 0u);
            const uint32_t bbase = bbase0 + ((term == 1) ? 16384u : 0u);
#pragma unroll
            for (int k16 = 0; k16 < 4; k16++) {
                uint32_t af[2][4], bf[4][4];
#pragma unroll
                for (int mi = 0; mi < 2; mi++) {
                    int ku = k16 * 2 + a_kq;
                    uint32_t addr = abase + arow[mi] * 128 + (((ku ^ (arow[mi] & 7))) << 4);
                    ldsm4(af[mi], addr);
                }
#pragma unroll
                for (int ni = 0; ni < 4; ni++) {
                    int ku = k16 * 2 + b_kq;
                    uint32_t addr = bbase + brow[ni] * 128 + (((ku ^ (brow[ni] & 7))) << 4);
                    ldsm4(bf[ni], addr);
                }
#pragma unroll
                for (int mi = 0; mi < 2; mi++)
#pragma unroll
                    for (int n8 = 0; n8 < 8; n8++)
                        mma16816(acc[mi][n8], af[mi], &bf[n8 >> 1][(n8 & 1) * 2]);
            }
        }
        if (kc < 3) store_A(s ^ 1);
    }

    const int fr = lane >> 2;
    const int fc = (lane & 3) * 2;
#pragma unroll
    for (int mi = 0; mi < 2; mi++) {
#pragma unroll
        for (int half = 0; half < 2; half++) {
            const int mrow = m0 + wm * 32 + mi * 16 + fr + half * 8;
            const int sr = mrow & (SS - 1);
#pragma unroll
            for (int n8 = 0; n8 < 8; n8++) {
                const int ncol = N0 + wn * 64 + n8 * 8 + fc;
                float v0 = acc[mi][n8][half * 2 + 0];
                float v1 = acc[mi][n8][half * 2 + 1];
                if (MODE == 0) {
                    float2 pe = *(const float2*)&g_pe[sr * DD + ncol];
                    v0 += pe.x; v1 += pe.y;
                } else {
                    float2 bb = *(const float2*)&bias[ncol];
                    float2 rr = *(const float2*)&resid[(size_t)mrow * DD + ncol];
                    float x0 = v0 + bb.x, x1 = v1 + bb.y;
                    v0 = 0.5f * x0 * (1.0f + erff(x0 * 0.70710678118654752f)) + rr.x;
                    v1 = 0.5f * x1 * (1.0f + erff(x1 * 0.70710678118654752f)) + rr.y;
                }
                float2 r = make_float2(v0, v1);
                *(float2*)&C[(size_t)mrow * DD + ncol] = r;
            }
        }
    }
}

// ---------------------------------------------------------------------------
// HMMA attention: 1 CTA per ray, 256 thr (8 warps).
// S = Qp Kp^T * scale (3-term bf16 split) -> softmax in fragments -> O = P V
// (3-term split, P hi/lo via smem, V via ldmatrix.trans).
// Smem (bf16, swizzled 16B-unit XOR): Qhi Qlo Khi Klo Vhi Vlo (32KB each).
// P hi/lo reuse the (dead) Q area after softmax.
// ---------------------------------------------------------------------------
#define ASM_Q_HI 0
#define ASM_Q_LO 32768
#define ASM_K_HI 65536
#define ASM_K_LO 98304
#define ASM_V_HI 131072
#define ASM_V_LO 163840
#define ASM_STAT 196608
#define ASM_P_HI 0
#define ASM_P_LO 8192
#define ATTN_SMEM (196608 + 1024)

__global__ void __launch_bounds__(256, 1) attn_hmma(
    const float* __restrict__ QP, const float* __restrict__ KP,
    const float* __restrict__ VP, float* __restrict__ AO)
{
    extern __shared__ char smem[];
    const uint32_t sbase = smem_to_u32(smem);
    const int t = threadIdx.x;
    const int wid = t >> 5, lane = t & 31;
    const int wm = wid >> 1, wn = wid & 1;
    const int q  = lane >> 3, r8 = lane & 7;
    const size_t base = (size_t)blockIdx.x * SS * DD;

    // ---- Load + split Q,K,V into smem (row stride 512B, unit swizzle) ----
    {
        const float* srcs[3] = { QP + base, KP + base, VP + base };
        const int dsts[3] = { ASM_Q_HI, ASM_K_HI, ASM_V_HI };
#pragma unroll
        for (int tz = 0; tz < 3; tz++) {
            char* hi = smem + dsts[tz];
            char* lo = hi + 32768;
            const float* src = srcs[tz];
#pragma unroll
            for (int g = 0; g < 16; g++) {
                int idx = g * 256 + t;        // 0..4095
                int row = idx >> 6;           // 64 rows
                int f4c = idx & 63;           // 64 float4 per row
                float4 v = *(const float4*)(src + row * DD + f4c * 4);
                __nv_bfloat16 hx = __float2bfloat16_rn(v.x);
                __nv_bfloat16 hy = __float2bfloat16_rn(v.y);
                __nv_bfloat16 hz = __float2bfloat16_rn(v.z);
                __nv_bfloat16 hw = __float2bfloat16_rn(v.w);
                uint16_t ux, uy, uz, uw;
                memcpy(&ux, &hx, 2); memcpy(&uy, &hy, 2);
                memcpy(&uz, &hz, 2); memcpy(&uw, &hw, 2);
                uint64_t hi64 = (uint64_t)((uint32_t)ux | ((uint32_t)uy << 16))
                              | ((uint64_t)((uint32_t)uz | ((uint32_t)uw << 16)) << 32);
                uint64_t lo64 = (uint64_t)pack2bf(v.x - __bfloat162float(hx),
                                                  v.y - __bfloat162float(hy))
                              | ((uint64_t)pack2bf(v.z - __bfloat162float(hz),
                                                   v.w - __bfloat162float(hw)) << 32);
                int u = f4c >> 1, half = f4c & 1;
                int d = row * 512 + ((u ^ (row & 7)) << 4) + half * 8;
                *(uint64_t*)(hi + d) = hi64;
                *(uint64_t*)(lo + d) = lo64;
            }
        }
    }
    __syncthreads();

    // ---- S-phase: warp tile 16(m) x 32(n), 3 terms ----
    const int arow = wm * 16 + r8 + (q & 1) * 8;
    const int a_ku = q >> 1;
    int brow[2];
#pragma unroll
    for (int ni = 0; ni < 2; ni++) brow[ni] = wn * 32 + ni * 16 + r8 + (q >> 1) * 8;
    const int b_ku = q & 1;

    float sacc[4][4];
#pragma unroll
    for (int i = 0; i < 4; i++)
#pragma unroll
        for (int c = 0; c < 4; c++) sacc[i][c] = 0.0f;

#pragma unroll
    for (int term = 0; term < 3; term++) {
        const uint32_t qb = sbase + ((term == 2) ? ASM_Q_LO : ASM_Q_HI);
        const uint32_t kb = sbase + ((term == 1) ? ASM_K_LO : ASM_K_HI);
#pragma unroll
        for (int k16 = 0; k16 < 16; k16++) {
            const int ku = k16 * 2;
            uint32_t af[4], bf[2][4];
            ldsm4(af, qb + arow * 512 + (((ku + a_ku) ^ (arow & 7)) << 4));
#pragma unroll
            for (int ni = 0; ni < 2; ni++)
                ldsm4(bf[ni], kb + brow[ni] * 512 + (((ku + b_ku) ^ (brow[ni] & 7)) << 4));
#pragma unroll
            for (int n8 = 0; n8 < 4; n8++)
                mma16816(sacc[n8], af, &bf[n8 >> 1][(n8 & 1) * 2]);
        }
    }

    // ---- Softmax in fragments ----
    float* stat = (float*)(smem + ASM_STAT);   // [0..127] max, [128..255] sum
    const int fr = lane >> 2;
    const int fc = (lane & 3) * 2;
    const int row0 = wm * 16 + fr;
    const int row1 = row0 + 8;

#pragma unroll
    for (int n8 = 0; n8 < 4; n8++)
#pragma unroll
        for (int c = 0; c < 4; c++) sacc[n8][c] *= 0.0625f;

    float m0 = -1e30f, m1 = -1e30f;
#pragma unroll
    for (int n8 = 0; n8 < 4; n8++) {
        m0 = fmaxf(m0, fmaxf(sacc[n8][0], sacc[n8][1]));
        m1 = fmaxf(m1, fmaxf(sacc[n8][2], sacc[n8][3]));
    }
    m0 = fmaxf(m0, __shfl_xor_sync(0xffffffffu, m0, 1));
    m0 = fmaxf(m0, __shfl_xor_sync(0xffffffffu, m0, 2));
    m1 = fmaxf(m1, __shfl_xor_sync(0xffffffffu, m1, 1));
    m1 = fmaxf(m1, __shfl_xor_sync(0xffffffffu, m1, 2));
    if ((lane & 3) == 0) {
        stat[row0 * 2 + wn] = m0;
        stat[row1 * 2 + wn] = m1;
    }
    __syncthreads();
    m0 = fmaxf(stat[row0 * 2], stat[row0 * 2 + 1]);
    m1 = fmaxf(stat[row1 * 2], stat[row1 * 2 + 1]);

    float s0 = 0.0f, s1 = 0.0f;
#pragma unroll
    for (int n8 = 0; n8 < 4; n8++) {
        float p0 = expf(sacc[n8][0] - m0); sacc[n8][0] = p0;
        float p1 = expf(sacc[n8][1] - m0); sacc[n8][1] = p1;
        float p2 = expf(sacc[n8][2] - m1); sacc[n8][2] = p2;
        float p3 = expf(sacc[n8][3] - m1); sacc[n8][3] = p3;
        s0 += p0 + p1; s1 += p2 + p3;
    }
    s0 += __shfl_xor_sync(0xffffffffu, s0, 1);
    s0 += __shfl_xor_sync(0xffffffffu, s0, 2);
    s1 += __shfl_xor_sync(0xffffffffu, s1, 1);
    s1 += __shfl_xor_sync(0xffffffffu, s1, 2);
    if ((lane & 3) == 0) {
        stat[128 + row0 * 2 + wn] = s0;
        stat[128 + row1 * 2 + wn] = s1;
    }
    __syncthreads();
    const float inv0 = 1.0f / (stat[128 + row0 * 2] + stat[128 + row0 * 2 + 1]);
    const float inv1 = 1.0f / (stat[128 + row1 * 2] + stat[128 + row1 * 2 + 1]);

    // ---- Write P (hi/lo split) into smem over dead Q area ----
    {
        char* phi = smem + ASM_P_HI;
        char* plo = smem + ASM_P_LO;
#pragma unroll
        for (int n8 = 0; n8 < 4; n8++) {
            const int j = wn * 32 + n8 * 8 + fc;
            const int u = j >> 3, b = (j & 7) * 2;
            // row0: c0,c1
            float p0 = sacc[n8][0] * inv0, p1 = sacc[n8][1] * inv0;
            __nv_bfloat16 h0 = __float2bfloat16_rn(p0);
            __nv_bfloat16 h1 = __float2bfloat16_rn(p1);
            uint16_t u0, u1; memcpy(&u0, &h0, 2); memcpy(&u1, &h1, 2);
            int off0 = row0 * 128 + ((u ^ (row0 & 7)) << 4) + b;
            *(uint32_t*)(phi + off0) = (uint32_t)u0 | ((uint32_t)u1 << 16);
            *(uint32_t*)(plo + off0) = pack2bf(p0 - __bfloat162float(h0),
                                               p1 - __bfloat162float(h1));
            // row1: c2,c3
            float p2 = sacc[n8][2] * inv1, p3 = sacc[n8][3] * inv1;
            __nv_bfloat16 h2 = __float2bfloat16_rn(p2);
            __nv_bfloat16 h3 = __float2bfloat16_rn(p3);
            uint16_t u2, u3; memcpy(&u2, &h2, 2); memcpy(&u3, &h3, 2);
            int off1 = row1 * 128 + ((u ^ (row1 & 7)) << 4) + b;
            *(uint32_t*)(phi + off1) = (uint32_t)u2 | ((uint32_t)u3 << 16);
            *(uint32_t*)(plo + off1) = pack2bf(p2 - __bfloat162float(h2),
                                               p3 - __bfloat162float(h3));
        }
    }
    __syncthreads();

    // ---- P@V phase: warp tile 16(m) x 128(d), k = 64(j), 3 terms ----
    float oacc[16][4];
#pragma unroll
    for (int i = 0; i < 16; i++)
#pragma unroll
        for (int c = 0; c < 4; c++) oacc[i][c] = 0.0f;

    const uint32_t phb = sbase + ASM_P_HI;
    const uint32_t plb = sbase + ASM_P_LO;
    const uint32_t vhb = sbase + ASM_V_HI;
    const uint32_t vlb = sbase + ASM_V_LO;
    const int arow2 = wm * 16 + r8 + (q & 1) * 8;   // P row for A frag

#pragma unroll
    for (int k16 = 0; k16 < 4; k16++) {
        uint32_t ph[4], pl[4];
        uint32_t aoff = arow2 * 128 + (((k16 * 2 + a_ku) ^ (arow2 & 7)) << 4);
        ldsm4(ph, phb + aoff);
        ldsm4(pl, plb + aoff);
        const int jrow = k16 * 16 + (q & 1) * 8 + r8;   // V row for B frag (trans)
#pragma unroll
        for (int d16 = 0; d16 < 8; d16++) {
            const int u = wn * 16 + d16 * 2 + (q >> 1);
            uint32_t voff = jrow * 512 + ((u ^ (jrow & 7)) << 4);
            uint32_t vh[4], vl[4];
            ldsm4t(vh, vhb + voff);
            ldsm4t(vl, vlb + voff);
            float* oA = oacc[d16 * 2];
            float* oB = oacc[d16 * 2 + 1];
            mma16816(oA, ph, &vh[0]);  mma16816(oB, ph, &vh[2]);
            mma16816(oA, ph, &vl[0]);  mma16816(oB, ph, &vl[2]);
            mma16816(oA, pl, &vh[0]);  mma16816(oB, pl, &vh[2]);
        }
    }

    // ---- Output: float2 stores straight from fragments ----
#pragma unroll
    for (int n8 = 0; n8 < 16; n8++) {
        const int d = wn * 128 + n8 * 8 + fc;
        *(float2*)&AO[base + (size_t)row0 * DD + d] = make_float2(oacc[n8][0], oacc[n8][1]);
        *(float2*)&AO[base + (size_t)row1 * DD + d] = make_float2(oacc[n8][2], oacc[n8][3]);
    }
}

// ---------------------------------------------------------------------------
extern "C" void kernel_launch(void* const* d_in, const int* in_sizes, int n_in,
                              void* d_out, int out_size) {
    (void)in_sizes; (void)n_in; (void)out_size;
    const float* q  = (const float*)d_in[0];
    const float* k  = (const float*)d_in[1];
    const float* v  = (const float*)d_in[2];
    const float* Wq = (const float*)d_in[3];
    const float* Wk = (const float*)d_in[4];
    const float* Wv = (const float*)d_in[5];
    const float* Wo = (const float*)d_in[6];
    const float* bo = (const float*)d_in[7];
    float* out = (float*)d_out;

    float *qp, *kp, *vp, *ao;
    cudaGetSymbolAddress((void**)&qp, g_qp);
    cudaGetSymbolAddress((void**)&kp, g_kp);
    cudaGetSymbolAddress((void**)&vp, g_vp);
    cudaGetSymbolAddress((void**)&ao, g_ao);
    __nv_bfloat16 *whi, *wlo;
    cudaGetSymbolAddress((void**)&whi, g_w_hi);
    cudaGetSymbolAddress((void**)&wlo, g_w_lo);

    posenc_kernel<<<(SS * DD + 255) / 256, 256>>>();
    wsplit_kernel<<<DD * DD / 256, 256>>>(Wq, whi + 0 * DD * DD, wlo + 0 * DD * DD);
    wsplit_kernel<<<DD * DD / 256, 256>>>(Wk, whi + 1 * DD * DD, wlo + 1 * DD * DD);
    wsplit_kernel<<<DD * DD / 256, 256>>>(Wv, whi + 2 * DD * DD, wlo + 2 * DD * DD);
    wsplit_kernel<<<DD * DD / 256, 256>>>(Wo, whi + 3 * DD * DD, wlo + 3 * DD * DD);

    cudaFuncSetAttribute(gemm_hmma<0>, cudaFuncAttributeMaxDynamicSharedMemorySize, GSMEM_TOTAL);
    cudaFuncSetAttribute(gemm_hmma<1>, cudaFuncAttributeMaxDynamicSharedMemorySize, GSMEM_TOTAL);
    cudaFuncSetAttribute(attn_hmma,    cudaFuncAttributeMaxDynamicSharedMemorySize, ATTN_SMEM);

    dim3 gg(M_TOTAL / 128, 2);
    gemm_hmma<0><<<gg, 256, GSMEM_TOTAL>>>(q, whi + 0 * DD * DD, wlo + 0 * DD * DD, qp, nullptr, nullptr);
    gemm_hmma<0><<<gg, 256, GSMEM_TOTAL>>>(k, whi + 1 * DD * DD, wlo + 1 * DD * DD, kp, nullptr, nullptr);
    gemm_hmma<0><<<gg, 256, GSMEM_TOTAL>>>(v, whi + 2 * DD * DD, wlo + 2 * DD * DD, vp, nullptr, nullptr);

    attn_hmma<<<VIEWS, 256, ATTN_SMEM>>>(qp, kp, vp, ao);

    gemm_hmma<1><<<gg, 256, GSMEM_TOTAL>>>(ao, whi + 3 * DD * DD, wlo + 3 * DD * DD, out, bo, q);
}